// round 6
// baseline (speedup 1.0000x reference)
#include <cuda_runtime.h>

// Problem dims (fixed by reference)
#define T0_R 8192
#define T0_C 4096
#define T1_R 4096
#define T1_C 2048
#define NG   1024
#define NMAP 512
#define CAP  128     // max rows per group; Binomial(8192,1/1024) max ~30, CAP=128 safe

// -------- device scratch (allocation-free, self-cleaning) --------
// Statically zero-initialized at module load; each call restores zeros:
//   d_cnt  : zeroed per-group by k_mega obsA blocks after consumption
//   d_p2   : zeroed by k_final after consumption
//   d_loss : zeroed by k_final after consumption
//   d_p1, d_lst : fully overwritten each call (no zeroing needed)
__device__ float  d_p2[T0_C];
__device__ float  d_p1[T1_R];
__device__ int    d_cnt[NG];
__device__ int    d_lst[NG * CAP];
__device__ double d_loss[2];         // [0]=sumsq loss_a, [1]=sumsq loss_b

// -------- block reduction (sum), result valid on thread 0 --------
__device__ __forceinline__ float block_reduce_sum(float v) {
    __shared__ float s[32];
    int lane = threadIdx.x & 31;
    int wid  = threadIdx.x >> 5;
    #pragma unroll
    for (int o = 16; o > 0; o >>= 1) v += __shfl_down_sync(0xffffffffu, v, o);
    if (lane == 0) s[wid] = v;
    __syncthreads();
    int nw = blockDim.x >> 5;
    v = (threadIdx.x < nw) ? s[threadIdx.x] : 0.0f;
    if (wid == 0) {
        #pragma unroll
        for (int o = 16; o > 0; o >>= 1) v += __shfl_down_sync(0xffffffffu, v, o);
    }
    return v;
}

// -------- 1) build per-group row lists (idx0 is int32; d_cnt arrives zeroed) --
__global__ void k_build(const int* __restrict__ idx0, int n_idx) {
    int i = blockIdx.x * blockDim.x + threadIdx.x;
    if (i < T0_R && i < n_idx) {
        int g = idx0[i];
        if (g < 0) g = 0;
        if (g >= NG) g = NG - 1;           // defensive clamp: no OOB ever
        int slot = atomicAdd(&d_cnt[g], 1);
        if (slot < CAP) d_lst[g * CAP + slot] = i;
    }
}

// -------- 2) mega kernel: blocks [0,NG) = obsA group sums; [NG,NG+T1_R) = p1 rows --
// obsA blocks are first in the grid so the long pole starts immediately; the
// 4096 p1 blocks backfill trailing waves, fully hidden under obsA's HBM stream.
__global__ void __launch_bounds__(256) k_mega(const float* __restrict__ theta0,
                                              const float* __restrict__ obs0,
                                              const float* __restrict__ theta1) {
    int t = threadIdx.x;
    int bid = blockIdx.x;

    if (bid < NG) {
        // ---- obsA: segment-sum of exp(theta0) over this group's rows ----
        int g = bid;
        int cnt = d_cnt[g];
        if (cnt > CAP) cnt = CAP;
        const int* rows = &d_lst[g * CAP];

        float4 acc[4];
        #pragma unroll
        for (int i = 0; i < 4; i++) acc[i] = make_float4(0.f, 0.f, 0.f, 0.f);

        for (int j = 0; j < cnt; j++) {
            int r = rows[j];
            if (r < 0 || r >= T0_R) continue;   // defensive
            const float4* tr = (const float4*)(theta0 + (size_t)r * T0_C);
            #pragma unroll
            for (int i = 0; i < 4; i++) {
                float4 v = tr[t + i * 256];
                acc[i].x += __expf(v.x);
                acc[i].y += __expf(v.y);
                acc[i].z += __expf(v.z);
                acc[i].w += __expf(v.w);
            }
        }

        const float4* orow = (const float4*)(obs0 + (size_t)g * T0_C);
        float local = 0.0f;
        #pragma unroll
        for (int i = 0; i < 4; i++) {
            float4 o = orow[t + i * 256];
            int c = (t + i * 256) * 4;
            atomicAdd(&d_p2[c + 0], acc[i].x);
            atomicAdd(&d_p2[c + 1], acc[i].y);
            atomicAdd(&d_p2[c + 2], acc[i].z);
            atomicAdd(&d_p2[c + 3], acc[i].w);
            float dx = o.x - acc[i].x;
            float dy = o.y - acc[i].y;
            float dz = o.z - acc[i].z;
            float dw = o.w - acc[i].w;
            local += dx * dx + dy * dy + dz * dz + dw * dw;
        }
        float tot = block_reduce_sum(local);
        if (t == 0) {
            atomicAdd(&d_loss[0], (double)tot);
            d_cnt[g] = 0;                      // self-clean for next call
        }
    } else {
        // ---- p1: row sum of exp(theta1) ----
        int r = bid - NG;
        const float4* tr = (const float4*)(theta1 + (size_t)r * T1_C);
        float local = 0.0f;
        #pragma unroll
        for (int i = 0; i < 2; i++) {
            float4 v = tr[t + i * 256];
            local += __expf(v.x) + __expf(v.y) + __expf(v.z) + __expf(v.w);
        }
        float tot = block_reduce_sum(local);
        if (t == 0) d_p1[r] = tot;
    }
}

// -------- 3) m1 = mapping1 @ p1, fused with loss_b. grid = NMAP blocks --------
__global__ void __launch_bounds__(256) k_obsB(const float* __restrict__ mapping1,
                                              const float* __restrict__ obs1) {
    int o = blockIdx.x;
    int t = threadIdx.x;
    const float4* mrow = (const float4*)(mapping1 + (size_t)o * T1_R);
    const float4* p1v  = (const float4*)d_p1;
    float local = 0.0f;
    #pragma unroll
    for (int i = 0; i < 4; i++) {
        float4 m = mrow[t + i * 256];
        float4 p = p1v[t + i * 256];
        local += m.x * p.x + m.y * p.y + m.z * p.z + m.w * p.w;
    }
    float tot = block_reduce_sum(local);
    if (t == 0) {
        float diff = obs1[o] - tot;
        atomicAdd(&d_loss[1], (double)(diff * diff));
    }
}

// -------- 4) loss_c from p2 + final combine; self-clean scratch --------
__global__ void __launch_bounds__(256) k_final(const float* __restrict__ obs2,
                                               float* __restrict__ out) {
    int t = threadIdx.x;
    float local = 0.0f;
    #pragma unroll
    for (int i = 0; i < T0_C / 256; i++) {
        int c = t + i * 256;
        float diff = obs2[c] - d_p2[c];
        local += diff * diff;
        d_p2[c] = 0.0f;                        // self-clean for next call
    }
    float tot = block_reduce_sum(local);
    if (t == 0) {
        double loss_a = d_loss[0] / ((double)NG * (double)T0_C);
        double loss_b = d_loss[1] / (double)NMAP;
        double loss_c = 0.5 * ((double)tot / (double)T0_C);
        out[0] = (float)((loss_a + loss_b + loss_c) / 3.0);
        d_loss[0] = 0.0;                       // self-clean for next call
        d_loss[1] = 0.0;
    }
}

extern "C" void kernel_launch(void* const* d_in, const int* in_sizes, int n_in,
                              void* d_out, int out_size) {
    const float* theta0   = (const float*)d_in[0];
    const float* theta1   = (const float*)d_in[1];
    const float* obs0     = (const float*)d_in[2];
    const float* obs1     = (const float*)d_in[3];
    const float* obs2     = (const float*)d_in[4];
    const int*   idx0     = (const int*)d_in[5];     // int32: JAX x64 disabled
    const float* mapping1 = (const float*)d_in[6];
    float* out = (float*)d_out;

    k_build<<<(T0_R + 255) / 256, 256>>>(idx0, in_sizes[5]);
    k_mega<<<NG + T1_R, 256>>>(theta0, obs0, theta1);
    k_obsB<<<NMAP, 256>>>(mapping1, obs1);
    k_final<<<1, 256>>>(obs2, out);
}

// round 7
// speedup vs baseline: 1.3989x; 1.3989x over previous
#include <cuda_runtime.h>

// Problem dims (fixed by reference)
#define T0_R 8192
#define T0_C 4096
#define T1_R 4096
#define T1_C 2048
#define NG   1024
#define NMAP 512
#define CAP  128       // max rows/group; Binomial(8192,1/1024) max ~25, CAP=128 safe
#define ATILE 4        // column tiles per group in k_obsA
#define ACOLS (T0_C / ATILE)       // 1024 cols per tile
#define LOSSC_BLKS 16  // extra blocks in k_obsB computing loss_c

// -------- device scratch (allocation-free, self-cleaning) --------
// Statically zero-init at load; invariant: every kernel_launch call both
// begins and ends with d_cnt/d_p2/d_loss zeroed.
//   d_cnt  : zeroed by k_final (after all obsA tiles have read it)
//   d_p2   : zeroed by k_obsB loss_c blocks (after consumption)
//   d_loss : zeroed by k_final (after consumption)
//   d_p1, d_lst : fully overwritten each call
__device__ float  d_p2[T0_C];
__device__ float  d_p1[T1_R];
__device__ int    d_cnt[NG];
__device__ int    d_lst[NG * CAP];
__device__ double d_loss[3];       // [0]=sumsq loss_a, [1]=sumsq loss_b, [2]=sumsq loss_c

// -------- block reduction (sum), result valid on thread 0 --------
__device__ __forceinline__ float block_reduce_sum(float v) {
    __shared__ float s[32];
    int lane = threadIdx.x & 31;
    int wid  = threadIdx.x >> 5;
    #pragma unroll
    for (int o = 16; o > 0; o >>= 1) v += __shfl_down_sync(0xffffffffu, v, o);
    if (lane == 0) s[wid] = v;
    __syncthreads();
    int nw = blockDim.x >> 5;
    v = (threadIdx.x < nw) ? s[threadIdx.x] : 0.0f;
    if (wid == 0) {
        #pragma unroll
        for (int o = 16; o > 0; o >>= 1) v += __shfl_down_sync(0xffffffffu, v, o);
    }
    return v;
}

// -------- 1) build per-group row lists (idx0 int32; d_cnt arrives zeroed) ----
__global__ void k_build(const int* __restrict__ idx0, int n_idx) {
    int i = blockIdx.x * blockDim.x + threadIdx.x;
    if (i < T0_R && i < n_idx) {
        int g = idx0[i];
        if (g < 0) g = 0;
        if (g >= NG) g = NG - 1;          // defensive clamp: no OOB ever
        int slot = atomicAdd(&d_cnt[g], 1);
        if (slot < CAP) d_lst[g * CAP + slot] = i;
    }
}

// -------- 2) obsA: (group, col-tile) work units. grid = NG*ATILE -----------
// unit u: g = u % NG, tile = u / NG. Each CTA: cnt rows x 1024 cols,
// 256 threads x 4 scalar accumulators. Straggler pole = slowest group / 4.
__global__ void __launch_bounds__(256) k_obsA(const float* __restrict__ theta0,
                                              const float* __restrict__ obs0) {
    int u = blockIdx.x;
    int g = u & (NG - 1);
    int tile = u >> 10;                   // u / NG
    int t = threadIdx.x;
    int c0 = tile * ACOLS;

    int cnt = d_cnt[g];
    if (cnt > CAP) cnt = CAP;
    const int* rows = &d_lst[g * CAP];

    float acc[4];
    #pragma unroll
    for (int i = 0; i < 4; i++) acc[i] = 0.0f;

    for (int j = 0; j < cnt; j++) {
        int r = rows[j];
        if (r < 0 || r >= T0_R) continue; // defensive
        const float* tr = theta0 + (size_t)r * T0_C + c0;
        #pragma unroll
        for (int i = 0; i < 4; i++) {
            acc[i] += __expf(tr[t + i * 256]);
        }
    }

    const float* orow = obs0 + (size_t)g * T0_C + c0;
    float local = 0.0f;
    #pragma unroll
    for (int i = 0; i < 4; i++) {
        int c = t + i * 256;
        atomicAdd(&d_p2[c0 + c], acc[i]);
        float diff = orow[c] - acc[i];
        local += diff * diff;
    }
    float tot = block_reduce_sum(local);
    if (t == 0) atomicAdd(&d_loss[0], (double)tot);
}

// -------- 3) p1 = rowsum of exp(theta1), float4. grid = T1_R ---------------
__global__ void __launch_bounds__(256) k_p1(const float* __restrict__ theta1) {
    int r = blockIdx.x;
    int t = threadIdx.x;
    const float4* tr = (const float4*)(theta1 + (size_t)r * T1_C);
    float4 v0 = tr[t];
    float4 v1 = tr[t + 256];
    float a0 = __expf(v0.x) + __expf(v0.y) + __expf(v0.z) + __expf(v0.w);
    float a1 = __expf(v1.x) + __expf(v1.y) + __expf(v1.z) + __expf(v1.w);
    float tot = block_reduce_sum(a0 + a1);
    if (t == 0) d_p1[r] = tot;
}

// -------- 4) obsB: blocks [0,NMAP) = mapping1 @ p1 + loss_b; ---------------
//            blocks [NMAP, NMAP+16) = loss_c slices + d_p2 self-clean
__global__ void __launch_bounds__(256) k_obsB(const float* __restrict__ mapping1,
                                              const float* __restrict__ obs1,
                                              const float* __restrict__ obs2) {
    int b = blockIdx.x;
    int t = threadIdx.x;
    if (b < NMAP) {
        const float4* mrow = (const float4*)(mapping1 + (size_t)b * T1_R);
        const float4* p1v  = (const float4*)d_p1;
        float local = 0.0f;
        #pragma unroll
        for (int i = 0; i < 4; i++) {
            float4 m = mrow[t + i * 256];
            float4 p = p1v[t + i * 256];
            local += m.x * p.x + m.y * p.y + m.z * p.z + m.w * p.w;
        }
        float tot = block_reduce_sum(local);
        if (t == 0) {
            float diff = obs1[b] - tot;
            atomicAdd(&d_loss[1], (double)(diff * diff));
        }
    } else {
        // loss_c slice: 256 cols per block
        int c = (b - NMAP) * 256 + t;
        float diff = obs2[c] - d_p2[c];
        d_p2[c] = 0.0f;                   // self-clean for next call
        float tot = block_reduce_sum(diff * diff);
        if (t == 0) atomicAdd(&d_loss[2], (double)tot);
    }
}

// -------- 5) final combine + scratch re-zero. 1 block, 256 threads ---------
__global__ void __launch_bounds__(256) k_final(float* __restrict__ out) {
    int t = threadIdx.x;
    // zero d_cnt for next call (all obsA tiles finished reading it)
    #pragma unroll
    for (int i = 0; i < NG / 256; i++) d_cnt[t + i * 256] = 0;
    if (t == 0) {
        double loss_a = d_loss[0] / ((double)NG * (double)T0_C);
        double loss_b = d_loss[1] / (double)NMAP;
        double loss_c = 0.5 * (d_loss[2] / (double)T0_C);
        out[0] = (float)((loss_a + loss_b + loss_c) / 3.0);
        d_loss[0] = 0.0;                  // self-clean for next call
        d_loss[1] = 0.0;
        d_loss[2] = 0.0;
    }
}

extern "C" void kernel_launch(void* const* d_in, const int* in_sizes, int n_in,
                              void* d_out, int out_size) {
    const float* theta0   = (const float*)d_in[0];
    const float* theta1   = (const float*)d_in[1];
    const float* obs0     = (const float*)d_in[2];
    const float* obs1     = (const float*)d_in[3];
    const float* obs2     = (const float*)d_in[4];
    const int*   idx0     = (const int*)d_in[5];   // int32: JAX x64 disabled
    const float* mapping1 = (const float*)d_in[6];
    float* out = (float*)d_out;

    k_build<<<(T0_R + 255) / 256, 256>>>(idx0, in_sizes[5]);
    k_obsA<<<NG * ATILE, 256>>>(theta0, obs0);
    k_p1<<<T1_R, 256>>>(theta1);
    k_obsB<<<NMAP + LOSSC_BLKS, 256>>>(mapping1, obs1, obs2);
    k_final<<<1, 256>>>(out);
}